// round 14
// baseline (speedup 1.0000x reference)
#include <cuda_runtime.h>
#include <cstdint>
#include <math.h>

// Problem shapes (fixed by the reference)
#define NB 8192          // batch
#define SS 10            // senses
#define HH 1024          // hidden
#define THREADS 128      // one block per row; 2 blocks/SM (smem-bound)
#define NBLOCKS 296      // 2 x 148
#define ALPHA_ROWS 16200 // 2700*6
#define ALPHA_CHUNKS 64
#define ALPHA_CHUNK 254  // 64*254 = 16256 >= 16200

#define SENT_BYTES 4096          // 1024 f32
#define GLOSS_BYTES 40960        // 10 x 1024 f32
#define ROW_BYTES (SENT_BYTES + GLOSS_BYTES)   // 45056
#define CTRL_BYTES 512
#define DYN_SMEM (2 * ROW_BYTES + CTRL_BYTES)  // 90624 -> 2 blocks/SM

// Scratch (device globals: no allocation allowed anywhere)
__device__ float g_margin_part[NB];
__device__ float g_alpha_part[ALPHA_CHUNKS];
__device__ unsigned int g_ticket;  // zero-init; self-resetting
__device__ unsigned int g_done;    // zero-init; self-resetting

__device__ __forceinline__ unsigned int smem_u32(const void* p) {
    return (unsigned int)__cvta_generic_to_shared(p);
}

__device__ __forceinline__ void mbar_init(unsigned int mbar, unsigned int cnt) {
    asm volatile("mbarrier.init.shared.b64 [%0], %1;" :: "r"(mbar), "r"(cnt) : "memory");
}
__device__ __forceinline__ void mbar_expect_tx(unsigned int mbar, unsigned int bytes) {
    asm volatile("mbarrier.arrive.expect_tx.shared.b64 _, [%0], %1;"
                 :: "r"(mbar), "r"(bytes) : "memory");
}
__device__ __forceinline__ void mbar_wait(unsigned int mbar, unsigned int parity) {
    asm volatile(
        "{\n\t"
        ".reg .pred P1;\n\t"
        "WAIT_LOOP_%=:\n\t"
        "mbarrier.try_wait.parity.acquire.cta.shared::cta.b64 P1, [%0], %1, 0x989680;\n\t"
        "@P1 bra.uni WAIT_DONE_%=;\n\t"
        "bra.uni WAIT_LOOP_%=;\n\t"
        "WAIT_DONE_%=:\n\t"
        "}"
        :: "r"(mbar), "r"(parity) : "memory");
}
// Non-tensor 1D bulk copy (TMA engine path; SASS UBLKCP) gmem -> smem.
__device__ __forceinline__ void bulk_g2s(unsigned int dst_smem, const void* src,
                                         unsigned int bytes, unsigned int mbar) {
    asm volatile(
        "cp.async.bulk.shared::cluster.global.mbarrier::complete_tx::bytes "
        "[%0], [%1], %2, [%3];"
        :: "r"(dst_smem), "l"(src), "r"(bytes), "r"(mbar) : "memory");
}

__global__ __launch_bounds__(THREADS)
void marginal_loss_fused(const float* __restrict__ sentence,
                         const float* __restrict__ gloss,
                         const float* __restrict__ alpha,
                         const int*   __restrict__ mask,
                         const int*   __restrict__ sids,
                         float* __restrict__ out, int out_size)
{
    extern __shared__ __align__(128) unsigned char smem[];
    float* buf0 = reinterpret_cast<float*>(smem);
    float* buf1 = reinterpret_cast<float*>(smem + ROW_BYTES);
    unsigned char* ctrl = smem + 2 * ROW_BYTES;
    // ctrl layout: [0:16) mbar[2], [16:20) ticket, [24:32) sid[2],
    //              [32:112) mask[2][10], [112:272) red[10][4], [272:276) last flag
    unsigned long long* mbar_p = reinterpret_cast<unsigned long long*>(ctrl);
    unsigned int*  s_ticket = reinterpret_cast<unsigned int*>(ctrl + 16);
    int*   s_sid  = reinterpret_cast<int*>(ctrl + 24);    // [2]
    int*   s_mask = reinterpret_cast<int*>(ctrl + 32);    // [2][10]
    float* s_red  = reinterpret_cast<float*>(ctrl + 112); // [10][4]
    int*   s_last = reinterpret_cast<int*>(ctrl + 272);

    const int tid  = threadIdx.x;
    const int lane = tid & 31;
    const int wid  = tid >> 5;
    const unsigned int mb0 = smem_u32(&mbar_p[0]);
    const unsigned int mb1 = smem_u32(&mbar_p[1]);

    if (tid == 0) { mbar_init(mb0, 1); mbar_init(mb1, 1); }
    __syncthreads();

    // ---- alpha prologue on blocks 0..63 (no smem-buffer interaction) ----
    if (blockIdx.x < ALPHA_CHUNKS) {
        const int c     = blockIdx.x;
        const int start = c * ALPHA_CHUNK;
        const int end   = min(start + ALPHA_CHUNK, ALPHA_ROWS);
        float part = 0.0f;
        for (int r = start + tid; r < end; r += THREADS) {
            const float* __restrict__ row = alpha + (size_t)r * 10;
            float s0 = 0.0f, mx = -1e30f;
            #pragma unroll
            for (int k = 0; k < 10; ++k) {
                float v = row[k];
                s0 += v;
                mx = fmaxf(mx, v);
            }
            part += (s0 == 0.0f) ? 0.0f : fabsf(mx - 1.0f);  // row_sum==0 -> 0
        }
        #pragma unroll
        for (int off = 16; off > 0; off >>= 1)
            part += __shfl_xor_sync(0xffffffffu, part, off);
        if (lane == 0) s_red[wid] = part;
        __syncthreads();
        if (tid == 0)
            g_alpha_part[c] = ((s_red[0] + s_red[1]) + (s_red[2] + s_red[3]));
        __syncthreads();
    }

    // ---- margin rows: block-per-row, whole-row TMA double buffer ----
    unsigned int t;
    if (tid == 0) *s_ticket = atomicAdd(&g_ticket, 1u);
    __syncthreads();
    t = *s_ticket;
    __syncthreads();

    int cb = 0;
    int ph0 = 0, ph1 = 0;

    if (t < NB) {
        // prime buffer 0 (thread 0 issues; meta by threads 0..10)
        if (tid == 0) {
            mbar_expect_tx(mb0, ROW_BYTES);
            bulk_g2s(smem_u32(buf0), sentence + (size_t)t * HH, SENT_BYTES, mb0);
            bulk_g2s(smem_u32(buf0) + SENT_BYTES, gloss + (size_t)t * SS * HH,
                     GLOSS_BYTES, mb0);
        }
        if (tid < SS) s_mask[0 * SS + tid] = mask[t * SS + tid];
        if (tid == SS) s_sid[0] = sids[t];
    }

    while (t < NB) {
        // fetch next ticket (one bar orders: prior consume-reads before the
        // prefetch below reuses the other buffer, and meta stores before reads)
        if (tid == 0) *s_ticket = atomicAdd(&g_ticket, 1u);
        __syncthreads();
        const unsigned int tn = *s_ticket;
        __syncthreads();

        const int nb = cb ^ 1;
        if (tn < NB) {
            float* nbuf = nb ? buf1 : buf0;
            if (tid == 0) {
                const unsigned int mb = nb ? mb1 : mb0;
                mbar_expect_tx(mb, ROW_BYTES);
                bulk_g2s(smem_u32(nbuf), sentence + (size_t)tn * HH, SENT_BYTES, mb);
                bulk_g2s(smem_u32(nbuf) + SENT_BYTES, gloss + (size_t)tn * SS * HH,
                         GLOSS_BYTES, mb);
            }
            if (tid < SS) s_mask[nb * SS + tid] = mask[tn * SS + tid];
            if (tid == SS) s_sid[nb] = sids[tn];
        }

        // wait for current buffer, consume
        if (cb == 0) { mbar_wait(mb0, ph0); ph0 ^= 1; }
        else         { mbar_wait(mb1, ph1); ph1 ^= 1; }

        const float* bufp = cb ? buf1 : buf0;
        const float4* sv4 = reinterpret_cast<const float4*>(bufp);
        const float4* gl4 = reinterpret_cast<const float4*>(bufp + HH);

        const float4 sv0 = sv4[tid];
        const float4 sv1 = sv4[tid + 128];

        float acc[SS];
        #pragma unroll
        for (int s = 0; s < SS; ++s) {
            const float4 g0 = gl4[s * 256 + tid];
            const float4 g1 = gl4[s * 256 + tid + 128];
            float d0 = sv0.x - g0.x + 1e-6f;
            float d1 = sv0.y - g0.y + 1e-6f;
            float d2 = sv0.z - g0.z + 1e-6f;
            float d3 = sv0.w - g0.w + 1e-6f;
            float a = 0.0f;
            a = fmaf(d0, d0, a); a = fmaf(d1, d1, a);
            a = fmaf(d2, d2, a); a = fmaf(d3, d3, a);
            d0 = sv1.x - g1.x + 1e-6f;
            d1 = sv1.y - g1.y + 1e-6f;
            d2 = sv1.z - g1.z + 1e-6f;
            d3 = sv1.w - g1.w + 1e-6f;
            a = fmaf(d0, d0, a); a = fmaf(d1, d1, a);
            a = fmaf(d2, d2, a); a = fmaf(d3, d3, a);
            acc[s] = a;
        }

        // block reduction: warp shfl, then fixed-order cross-warp (deterministic)
        #pragma unroll
        for (int s = 0; s < SS; ++s) {
            float v = acc[s];
            #pragma unroll
            for (int off = 16; off > 0; off >>= 1)
                v += __shfl_xor_sync(0xffffffffu, v, off);
            if (lane == 0) s_red[s * 4 + wid] = v;
        }
        __syncthreads();

        if (wid == 0) {
            float tot = 0.0f;
            if (lane < SS) {
                #pragma unroll
                for (int w = 0; w < 4; ++w) tot += s_red[lane * 4 + w];
            }
            if (lane == 0) {
                const int sid = s_sid[cb];
                float pos  = 0.0f;
                float minv = 1e30f;   // strict < == argmin first-index tie rule
                float neg  = 0.0f;
                #pragma unroll
                for (int s = 0; s < SS; ++s) {
                    float ds = sqrtf(__shfl_sync(0xffffffffu, tot, s));
                    if (s == sid) pos = ds;
                    bool valid = (s_mask[cb * SS + s] != 0) && (s != sid);
                    float m = valid ? ds : 10.0f;          // SENTINEL
                    if (m < minv) { minv = m; neg = ds; }  // carry REAL dist at argmin
                }
                g_margin_part[t] = fmaxf(pos - neg + 0.5f, 0.0f);
            } else {
                #pragma unroll
                for (int s = 0; s < SS; ++s)
                    (void)__shfl_sync(0xffffffffu, tot, s);
            }
        }
        __syncthreads();   // s_red reusable; consume of buf[cb] complete

        cb = nb;
        t = tn;
    }

    // ---- completion-counter fused finalize (last block only) ----
    if (tid == 0) {
        __threadfence();
        unsigned int d = atomicAdd(&g_done, 1u);
        *s_last = (d == (unsigned int)(gridDim.x - 1)) ? 1 : 0;
    }
    __syncthreads();
    if (*s_last == 0) return;

    // margin sum, fixed order -> bit-deterministic (reuse buf0 as scratch)
    float* sh = buf0;
    float m = 0.0f;
    for (int i = tid; i < NB; i += THREADS) m += g_margin_part[i];
    sh[tid] = m;
    __syncthreads();
    #pragma unroll
    for (int off = THREADS / 2; off > 0; off >>= 1) {
        if (tid < off) sh[tid] += sh[tid + off];
        __syncthreads();
    }
    float margin = sh[0];
    __syncthreads();

    sh[tid] = (tid < ALPHA_CHUNKS) ? g_alpha_part[tid] : 0.0f;
    __syncthreads();
    #pragma unroll
    for (int off = THREADS / 2; off > 0; off >>= 1) {
        if (tid < off) sh[tid] += sh[tid + off];
        __syncthreads();
    }
    float alpha_term = sh[0];

    if (tid == 0) {
        float loss = margin * 0.875f + alpha_term * 0.125f;
        out[0] = loss;
        if (out_size > 1) out[1] = margin;
        if (out_size > 2) out[2] = alpha_term;
        // self-reset for next graph replay
        g_ticket = 0u;
        g_done   = 0u;
    }
}

extern "C" void kernel_launch(void* const* d_in, const int* in_sizes, int n_in,
                              void* d_out, int out_size)
{
    // Identify inputs robustly by element count (all distinct):
    //   sentence  8192*1024    = 8388608  (f32)
    //   all_gloss 8192*10*1024 = 83886080 (f32)
    //   alpha     2700*6*10    = 162000   (f32)
    //   sense_mask 8192*10     = 81920    (i32)
    //   sense_ids 8192         = 8192     (i32)
    const float* sentence = nullptr;
    const float* gloss    = nullptr;
    const float* alpha    = nullptr;
    const int*   mask     = nullptr;
    const int*   sids     = nullptr;
    for (int i = 0; i < n_in; ++i) {
        switch (in_sizes[i]) {
            case 8388608:  sentence = (const float*)d_in[i]; break;
            case 83886080: gloss    = (const float*)d_in[i]; break;
            case 162000:   alpha    = (const float*)d_in[i]; break;
            case 81920:    mask     = (const int*)  d_in[i]; break;
            case 8192:     sids     = (const int*)  d_in[i]; break;
            default: break;
        }
    }

    static int attr_done = 0;
    if (!attr_done) {
        cudaFuncSetAttribute(marginal_loss_fused,
                             cudaFuncAttributeMaxDynamicSharedMemorySize, DYN_SMEM);
        attr_done = 1;
    }

    marginal_loss_fused<<<NBLOCKS, THREADS, DYN_SMEM>>>(
        sentence, gloss, alpha, mask, sids, (float*)d_out, out_size);
}

// round 15
// speedup vs baseline: 2.0035x; 2.0035x over previous
#include <cuda_runtime.h>
#include <cstdint>
#include <math.h>

// Problem shapes (fixed by the reference)
#define NB 8192          // batch
#define SS 10            // senses
#define HH 1024          // hidden
#define THREADS 64       // 2 warps/block (static-smem sized)
#define WARPS 2
#define NBLOCKS 740      // 5 blocks/SM x 148; tickets balance any residency
#define ALPHA_ROWS 16200 // 2700*6
#define ALPHA_CHUNKS 64
#define ALPHA_CHUNK 254  // 64*254 = 16256 >= 16200
#define NTICKETS (NB + ALPHA_CHUNKS)

#define NSTAGE 4
#define STAGE_BYTES (11 * 512)   // sentence(512B) + 10 senses(512B) per j-step

// Scratch (device globals: no allocation allowed anywhere)
__device__ float g_margin_part[NB];
__device__ float g_alpha_part[ALPHA_CHUNKS];
__device__ unsigned int g_ticket;  // zero-init; self-resetting
__device__ unsigned int g_done;    // zero-init; self-resetting

// 256B L2 fetch granularity: halves DRAM request count on this fully
// sequential stream (512B-contiguous chunks per lane-group -> no waste)
#define CP_ASYNC16(dst_smem, src_gmem) \
    asm volatile("cp.async.cg.shared.global.L2::256B [%0], [%1], 16;" \
                 :: "r"(dst_smem), "l"(src_gmem) : "memory")
#define CP_COMMIT() asm volatile("cp.async.commit_group;" ::: "memory")
#define CP_WAIT3()  asm volatile("cp.async.wait_group 3;" ::: "memory")
#define CP_WAIT0()  asm volatile("cp.async.wait_group 0;" ::: "memory")

// Issue one j-step stage for row b into smem at smem_base (same-lane staging).
__device__ __forceinline__ void issue_stage(const float* __restrict__ sentence,
                                            const float* __restrict__ gloss,
                                            int b, int j, unsigned int smem_base, int lane)
{
    const float4* s = reinterpret_cast<const float4*>(sentence + (size_t)b * HH)
                      + j * 32 + lane;
    CP_ASYNC16(smem_base + lane * 16, s);
    const float4* g0 = reinterpret_cast<const float4*>(gloss + (size_t)b * SS * HH)
                       + j * 32 + lane;
    #pragma unroll
    for (int l = 0; l < SS; ++l)
        CP_ASYNC16(smem_base + (l + 1) * 512 + lane * 16, g0 + l * 256);
}

__global__ __launch_bounds__(THREADS)
void marginal_loss_fused(const float* __restrict__ sentence,
                         const float* __restrict__ gloss,
                         const float* __restrict__ alpha,
                         const int*   __restrict__ mask,
                         const int*   __restrict__ sids,
                         float* __restrict__ out, int out_size)
{
    const int lane = threadIdx.x & 31;
    const int warp = threadIdx.x >> 5;

    __shared__ __align__(16) char stage_buf[WARPS][NSTAGE][STAGE_BYTES];

    const unsigned int wbase =
        (unsigned int)__cvta_generic_to_shared(&stage_buf[warp][0][0]);

    // first ticket
    unsigned int t;
    if (lane == 0) t = atomicAdd(&g_ticket, 1u);
    t = __shfl_sync(0xffffffffu, t, 0);
    bool primed = false;   // true iff stages 0..2 of row t already committed

    while (t < NTICKETS) {
        if (t < NB) {
            const int b = (int)t;
            if (!primed) {
                #pragma unroll
                for (int k = 0; k < 3; ++k) {
                    issue_stage(sentence, gloss, b, k, wbase + k * STAGE_BYTES, lane);
                    CP_COMMIT();
                }
            }

            float acc[SS];
            #pragma unroll
            for (int s = 0; s < SS; ++s) acc[s] = 0.0f;

            unsigned int tn = NTICKETS;  // next ticket, fetched at j==5

            // Pipeline invariant: one commit per iteration; before consuming
            // stage j, the 3 newest groups are stages j+1..j+3 (possibly empty)
            // -> wait_group 3 guarantees stage j's group has completed.
            #pragma unroll
            for (int j = 0; j < 8; ++j) {
                const int pj = j + 3;            // prefetch target
                if (pj < 8) {
                    issue_stage(sentence, gloss, b, pj,
                                wbase + (pj & 3) * STAGE_BYTES, lane);
                } else {
                    const int k = pj - 8;        // next row's stage 0,1,2
                    if (k == 0) {
                        if (lane == 0) tn = atomicAdd(&g_ticket, 1u);
                        tn = __shfl_sync(0xffffffffu, tn, 0);
                    }
                    if (tn < NB)
                        issue_stage(sentence, gloss, (int)tn, k,
                                    wbase + (k & 3) * STAGE_BYTES, lane);
                    // else: empty group keeps the positional invariant
                }
                CP_COMMIT();
                CP_WAIT3();

                // consume stage j (same-lane data -> no syncwarp needed)
                const float4* p = reinterpret_cast<const float4*>(
                    &stage_buf[warp][j & 3][0]);
                const float4 sv = p[lane];
                #pragma unroll
                for (int s = 0; s < SS; ++s) {
                    float4 g = p[(s + 1) * 32 + lane];
                    float d0 = sv.x - g.x + 1e-6f;
                    float d1 = sv.y - g.y + 1e-6f;
                    float d2 = sv.z - g.z + 1e-6f;
                    float d3 = sv.w - g.w + 1e-6f;
                    float a = acc[s];
                    a = fmaf(d0, d0, a);
                    a = fmaf(d1, d1, a);
                    a = fmaf(d2, d2, a);
                    a = fmaf(d3, d3, a);
                    acc[s] = a;
                }
            }

            // epilogue (next row's stages 0..2 are in flight during this)
            #pragma unroll
            for (int s = 0; s < SS; ++s) {
                float v = acc[s];
                #pragma unroll
                for (int off = 16; off > 0; off >>= 1)
                    v += __shfl_xor_sync(0xffffffffu, v, off);
                acc[s] = v;
            }

            if (lane == 0) {
                const int sid = sids[b];
                float pos  = 0.0f;
                float minv = 1e30f;   // first strict-< win == argmin first-index tie rule
                float neg  = 0.0f;
                #pragma unroll
                for (int s = 0; s < SS; ++s) {
                    float ds = sqrtf(acc[s]);
                    if (s == sid) pos = ds;
                    bool valid = (mask[b * SS + s] != 0) && (s != sid);
                    float m = valid ? ds : 10.0f;          // SENTINEL
                    if (m < minv) { minv = m; neg = ds; }  // carry REAL distance at argmin
                }
                g_margin_part[b] = fmaxf(pos - neg + 0.5f, 0.0f);
            }

            primed = (tn < NB);
            t = tn;
        } else {
            // ---- alpha chunk (plain loads; pending empty groups harmless) ----
            const int c     = (int)(t - NB);
            const int start = c * ALPHA_CHUNK;
            const int end   = min(start + ALPHA_CHUNK, ALPHA_ROWS);
            float part = 0.0f;
            for (int r = start + lane; r < end; r += 32) {
                const float* __restrict__ row = alpha + (size_t)r * 10;
                float s0 = 0.0f, mx = -1e30f;
                #pragma unroll
                for (int k = 0; k < 10; ++k) {
                    float v = row[k];
                    s0 += v;
                    mx = fmaxf(mx, v);
                }
                // row_sum==0 -> tmp=ones -> max=1 -> |1-1| = 0
                part += (s0 == 0.0f) ? 0.0f : fabsf(mx - 1.0f);
            }
            #pragma unroll
            for (int off = 16; off > 0; off >>= 1)
                part += __shfl_xor_sync(0xffffffffu, part, off);
            if (lane == 0) g_alpha_part[c] = part;

            if (lane == 0) t = atomicAdd(&g_ticket, 1u);
            t = __shfl_sync(0xffffffffu, t, 0);
            primed = false;
        }
    }

    // drain ALL outstanding cp.async groups before finalize / exit
    CP_WAIT0();

    // ---- completion-counter fused finalize (last block only) ----
    __shared__ bool s_last;
    __syncthreads();
    if (threadIdx.x == 0) {
        __threadfence();
        unsigned int d = atomicAdd(&g_done, 1u);
        s_last = (d == (unsigned int)(gridDim.x - 1));
    }
    __syncthreads();
    if (!s_last) return;

    __shared__ float sh[THREADS];

    // margin sum, fixed order -> bit-deterministic
    float m = 0.0f;
    for (int i = threadIdx.x; i < NB; i += THREADS) m += g_margin_part[i];
    sh[threadIdx.x] = m;
    __syncthreads();
    #pragma unroll
    for (int off = THREADS / 2; off > 0; off >>= 1) {
        if (threadIdx.x < off) sh[threadIdx.x] += sh[threadIdx.x + off];
        __syncthreads();
    }
    float margin = sh[0];
    __syncthreads();

    // alpha sum
    float a = (threadIdx.x < ALPHA_CHUNKS) ? g_alpha_part[threadIdx.x] : 0.0f;
    sh[threadIdx.x] = a;
    __syncthreads();
    #pragma unroll
    for (int off = THREADS / 2; off > 0; off >>= 1) {
        if (threadIdx.x < off) sh[threadIdx.x] += sh[threadIdx.x + off];
        __syncthreads();
    }
    float alpha_term = sh[0];

    if (threadIdx.x == 0) {
        float loss = margin * 0.875f + alpha_term * 0.125f;
        out[0] = loss;
        if (out_size > 1) out[1] = margin;
        if (out_size > 2) out[2] = alpha_term;
        // self-reset for next graph replay (stream order guarantees visibility)
        g_ticket = 0u;
        g_done   = 0u;
    }
}

extern "C" void kernel_launch(void* const* d_in, const int* in_sizes, int n_in,
                              void* d_out, int out_size)
{
    // Identify inputs robustly by element count (all distinct):
    //   sentence  8192*1024    = 8388608  (f32)
    //   all_gloss 8192*10*1024 = 83886080 (f32)
    //   alpha     2700*6*10    = 162000   (f32)
    //   sense_mask 8192*10     = 81920    (i32)
    //   sense_ids 8192         = 8192     (i32)
    const float* sentence = nullptr;
    const float* gloss    = nullptr;
    const float* alpha    = nullptr;
    const int*   mask     = nullptr;
    const int*   sids     = nullptr;
    for (int i = 0; i < n_in; ++i) {
        switch (in_sizes[i]) {
            case 8388608:  sentence = (const float*)d_in[i]; break;
            case 83886080: gloss    = (const float*)d_in[i]; break;
            case 162000:   alpha    = (const float*)d_in[i]; break;
            case 81920:    mask     = (const int*)  d_in[i]; break;
            case 8192:     sids     = (const int*)  d_in[i]; break;
            default: break;
        }
    }

    marginal_loss_fused<<<NBLOCKS, THREADS>>>(sentence, gloss, alpha, mask, sids,
                                              (float*)d_out, out_size);
}